// round 5
// baseline (speedup 1.0000x reference)
#include <cuda_runtime.h>
#include <math_constants.h>

#define BB 4
#define TT 2048
#define CC 1024
#define HH 16
#define DD 64
#define BTOT (BB*TT)          // 8192 rows

// Scratch (allocation-free rule: __device__ globals)
__device__ float g_qkv[(size_t)BTOT * 3 * CC];   // [B*T, 3C] = qkv projection output
__device__ float g_attn[(size_t)BTOT * CC];      // [B*T, C]  = attention output

// ---------------------------------------------------------------------------
// Generic fp32 GEMM + bias:  out[M,N] = A[M,K] @ W[K,N] + bias[N]
// 128x128 block tile, BK=8, 256 threads, 8x8 per-thread microtile.
// Requires M%128==0, N%128==0, K%8==0 (true for all our shapes).
// ---------------------------------------------------------------------------
__global__ __launch_bounds__(256)
void gemm_bias_kernel(const float* __restrict__ A, const float* __restrict__ W,
                      const float* __restrict__ bias, float* __restrict__ out,
                      int M, int N, int K)
{
    __shared__ float As[8][128];   // transposed A tile: As[k][m]
    __shared__ float Bs[8][128];   // Bs[k][n]

    const int tid  = threadIdx.x;
    const int row0 = blockIdx.y * 128;
    const int col0 = blockIdx.x * 128;

    // A-tile load: 128 rows x 8 cols, each thread one float4
    const int a_row = tid >> 1;          // 0..127
    const int a_col = (tid & 1) << 2;    // 0 or 4
    // B-tile load: 8 rows x 128 cols, each thread one float4
    const int b_row = tid >> 5;          // 0..7
    const int b_col = (tid & 31) << 2;   // 0..124

    const int ty = tid >> 4;             // 0..15 -> rows ty*8..ty*8+7
    const int tx = tid & 15;             // 0..15 -> cols tx*8..tx*8+7

    float acc[8][8];
    #pragma unroll
    for (int i = 0; i < 8; i++)
        #pragma unroll
        for (int j = 0; j < 8; j++) acc[i][j] = 0.f;

    const float* Aptr = A + (size_t)(row0 + a_row) * K + a_col;
    const float* Wptr = W + (size_t)b_row * N + (col0 + b_col);

    for (int k0 = 0; k0 < K; k0 += 8) {
        float4 av = *(const float4*)(Aptr + k0);
        float4 bv = *(const float4*)(Wptr + (size_t)k0 * N);
        As[a_col + 0][a_row] = av.x;
        As[a_col + 1][a_row] = av.y;
        As[a_col + 2][a_row] = av.z;
        As[a_col + 3][a_row] = av.w;
        *(float4*)&Bs[b_row][b_col] = bv;
        __syncthreads();

        #pragma unroll
        for (int kk = 0; kk < 8; kk++) {
            float ar[8], br[8];
            *(float4*)&ar[0] = *(const float4*)&As[kk][ty * 8];
            *(float4*)&ar[4] = *(const float4*)&As[kk][ty * 8 + 4];
            *(float4*)&br[0] = *(const float4*)&Bs[kk][tx * 8];
            *(float4*)&br[4] = *(const float4*)&Bs[kk][tx * 8 + 4];
            #pragma unroll
            for (int i = 0; i < 8; i++)
                #pragma unroll
                for (int j = 0; j < 8; j++)
                    acc[i][j] += ar[i] * br[j];
        }
        __syncthreads();
    }

    // Epilogue: bias + store (float4)
    #pragma unroll
    for (int i = 0; i < 8; i++) {
        const int m = row0 + ty * 8 + i;
        #pragma unroll
        for (int j = 0; j < 8; j += 4) {
            const int n = col0 + tx * 8 + j;
            float4 r;
            r.x = acc[i][j + 0] + bias[n + 0];
            r.y = acc[i][j + 1] + bias[n + 1];
            r.z = acc[i][j + 2] + bias[n + 2];
            r.w = acc[i][j + 3] + bias[n + 3];
            *(float4*)&out[(size_t)m * N + n] = r;
        }
    }
}

// ---------------------------------------------------------------------------
// Flash-style causal attention, fp32.
// Grid: (T/BQ, B*H). Block: 128 threads; thread t owns q-row (q0 + t).
// qkv layout: [B*T, 3C]; q at col h*D, k at C + h*D, v at 2C + h*D.
// out: g_attn [B*T, C], head h occupies cols h*D..h*D+63.
// ---------------------------------------------------------------------------
#define BQ  128
#define BKV 32

__global__ __launch_bounds__(128)
void attn_kernel(const float* __restrict__ qkv, float* __restrict__ out)
{
    const int bh = blockIdx.y;                // 0..63
    const int b  = bh / HH;
    const int h  = bh % HH;
    const int q0 = blockIdx.x * BQ;
    const int tid = threadIdx.x;
    const int qrow = q0 + tid;                // this thread's query index

    __shared__ float Ks[BKV][DD];
    __shared__ float Vs[BKV][DD];

    // Load Q row into registers
    float qreg[DD];
    {
        const float* qp = qkv + ((size_t)(b * TT + qrow)) * (3 * CC) + h * DD;
        #pragma unroll
        for (int d = 0; d < DD; d += 4)
            *(float4*)&qreg[d] = *(const float4*)&qp[d];
    }

    float oacc[DD];
    #pragma unroll
    for (int d = 0; d < DD; d++) oacc[d] = 0.f;
    float mmax = -CUDART_INF_F;
    float lsum = 0.f;

    const float scale = 0.125f;   // 1/sqrt(64)
    const int kv_end = q0 + BQ;   // causal: no kv beyond last q row of this block

    for (int kv0 = 0; kv0 < kv_end; kv0 += BKV) {
        // Cooperative K/V tile load: BKV*DD/4 = 512 float4 pairs, 128 threads
        #pragma unroll
        for (int idx = tid; idx < BKV * DD / 4; idx += 128) {
            const int j  = idx >> 4;           // row within tile
            const int dd = (idx & 15) << 2;    // float4 offset
            const float* kp = qkv + ((size_t)(b * TT + kv0 + j)) * (3 * CC) + CC + h * DD + dd;
            *(float4*)&Ks[j][dd] = *(const float4*)kp;
            *(float4*)&Vs[j][dd] = *(const float4*)(kp + CC);
        }
        __syncthreads();

        // Scores for this tile
        float s[BKV];
        float tilemax = -CUDART_INF_F;
        #pragma unroll
        for (int j = 0; j < BKV; j++) {
            float acc = 0.f;
            #pragma unroll
            for (int d = 0; d < DD; d += 4) {
                float4 k4 = *(const float4*)&Ks[j][d];
                acc += qreg[d + 0] * k4.x;
                acc += qreg[d + 1] * k4.y;
                acc += qreg[d + 2] * k4.z;
                acc += qreg[d + 3] * k4.w;
            }
            s[j] = (kv0 + j <= qrow) ? acc * scale : -CUDART_INF_F;
            tilemax = fmaxf(tilemax, s[j]);
        }

        // Online softmax update
        const float newmax = fmaxf(mmax, tilemax);
        const float corr = __expf(mmax - newmax);   // exp(-inf)=0 on first tile
        lsum *= corr;
        #pragma unroll
        for (int d = 0; d < DD; d++) oacc[d] *= corr;

        #pragma unroll
        for (int j = 0; j < BKV; j++) {
            const float p = __expf(s[j] - newmax);
            lsum += p;
            #pragma unroll
            for (int d = 0; d < DD; d += 4) {
                float4 v4 = *(const float4*)&Vs[j][d];
                oacc[d + 0] += p * v4.x;
                oacc[d + 1] += p * v4.y;
                oacc[d + 2] += p * v4.z;
                oacc[d + 3] += p * v4.w;
            }
        }
        mmax = newmax;
        __syncthreads();
    }

    // Normalize and store
    const float inv = 1.f / lsum;
    float* op = out + ((size_t)(b * TT + qrow)) * CC + h * DD;
    #pragma unroll
    for (int d = 0; d < DD; d += 4) {
        float4 r;
        r.x = oacc[d + 0] * inv;
        r.y = oacc[d + 1] * inv;
        r.z = oacc[d + 2] * inv;
        r.w = oacc[d + 3] * inv;
        *(float4*)&op[d] = r;
    }
}

// ---------------------------------------------------------------------------
// Launch
// ---------------------------------------------------------------------------
extern "C" void kernel_launch(void* const* d_in, const int* in_sizes, int n_in,
                              void* d_out, int out_size)
{
    const float* hidden = (const float*)d_in[0];   // [B,T,C]
    const float* qkv_w  = (const float*)d_in[1];   // [C, 3C]
    const float* qkv_b  = (const float*)d_in[2];   // [3C]
    const float* o_w    = (const float*)d_in[3];   // [C, C]
    const float* o_b    = (const float*)d_in[4];   // [C]
    float* out = (float*)d_out;                    // [B,T,C]

    float* qkv;  cudaGetSymbolAddress((void**)&qkv,  g_qkv);
    float* attn; cudaGetSymbolAddress((void**)&attn, g_attn);

    // 1) QKV projection: [8192,1024] @ [1024,3072] + bias -> g_qkv
    {
        dim3 grid(3 * CC / 128, BTOT / 128);
        gemm_bias_kernel<<<grid, 256>>>(hidden, qkv_w, qkv_b, qkv, BTOT, 3 * CC, CC);
    }
    // 2) Causal multi-head attention -> g_attn
    {
        dim3 grid(TT / BQ, BB * HH);
        attn_kernel<<<grid, 128>>>(qkv, attn);
    }
    // 3) Output projection: [8192,1024] @ [1024,1024] + bias -> d_out
    {
        dim3 grid(CC / 128, BTOT / 128);
        gemm_bias_kernel<<<grid, 256>>>(attn, o_w, o_b, out, BTOT, CC, CC);
    }
}

// round 6
// speedup vs baseline: 1.2904x; 1.2904x over previous
#include <cuda_runtime.h>
#include <math_constants.h>

#define BB 4
#define TT 2048
#define CC 1024
#define HH 16
#define DD 64
#define BTOT (BB*TT)          // 8192 rows

// Scratch (allocation-free rule: __device__ globals)
__device__ float g_qkv[(size_t)BTOT * 3 * CC];   // [B*T, 3C]
__device__ float g_attn[(size_t)BTOT * CC];      // [B*T, C]

__device__ __forceinline__ unsigned f2tf32(float x) {
    unsigned y;
    asm("cvt.rna.tf32.f32 %0, %1;" : "=r"(y) : "f"(x));
    return y;
}

__device__ __forceinline__ void mma_tf32(float d[4], const unsigned a[4], const unsigned b[2]) {
    asm volatile(
        "mma.sync.aligned.m16n8k8.row.col.f32.tf32.tf32.f32 "
        "{%0,%1,%2,%3}, {%4,%5,%6,%7}, {%8,%9}, {%0,%1,%2,%3};"
        : "+f"(d[0]), "+f"(d[1]), "+f"(d[2]), "+f"(d[3])
        : "r"(a[0]), "r"(a[1]), "r"(a[2]), "r"(a[3]), "r"(b[0]), "r"(b[1]));
}

// ---------------------------------------------------------------------------
// TF32 tensor-core GEMM + bias: out[M,N] = A[M,K] @ W[K,N] + bias[N]
// 128x128x32 block tile, 256 threads (8 warps, 2x4 warp grid, 64x32 warp tile).
// Smem k-major with stride 136 (=> 8k+idx mod 32 bank pattern, conflict-free
// fragment loads). Requires M%128==0, N%128==0, K%32==0.
// ---------------------------------------------------------------------------
#define SMS 136   // smem row stride in floats (136 % 32 == 8)

__global__ __launch_bounds__(256)
void gemm_tf32_kernel(const float* __restrict__ A, const float* __restrict__ W,
                      const float* __restrict__ bias, float* __restrict__ out,
                      int M, int N, int K)
{
    __shared__ unsigned As[32][SMS];   // As[k][m]
    __shared__ unsigned Bs[32][SMS];   // Bs[k][n]

    const int tid  = threadIdx.x;
    const int lane = tid & 31;
    const int warp = tid >> 5;
    const int row0 = blockIdx.y * 128;
    const int col0 = blockIdx.x * 128;

    const int wm = (warp >> 2) * 64;   // warp row offset within block tile
    const int wn = (warp & 3) * 32;    // warp col offset within block tile

    // Global load mapping
    const int a_row = tid >> 1;            // 0..127
    const int a_kb  = (tid & 1) * 16;      // k base: 0 or 16
    const int b_row = tid >> 3;            // 0..31  (k within tile)
    const int b_nb  = (tid & 7) * 16;      // n base: 0..112

    const float* Ap = A + (size_t)(row0 + a_row) * K + a_kb;
    const float* Wp = W + (size_t)b_row * N + col0 + b_nb;

    float d[4][4][4];
    #pragma unroll
    for (int mi = 0; mi < 4; mi++)
        #pragma unroll
        for (int ni = 0; ni < 4; ni++)
            #pragma unroll
            for (int j = 0; j < 4; j++) d[mi][ni][j] = 0.f;

    for (int k0 = 0; k0 < K; k0 += 32) {
        // --- stage A tile (transposed into k-major) with tf32 conversion ---
        #pragma unroll
        for (int i = 0; i < 4; i++) {
            float4 av = *(const float4*)(Ap + k0 + i * 4);
            As[a_kb + i * 4 + 0][a_row] = f2tf32(av.x);
            As[a_kb + i * 4 + 1][a_row] = f2tf32(av.y);
            As[a_kb + i * 4 + 2][a_row] = f2tf32(av.z);
            As[a_kb + i * 4 + 3][a_row] = f2tf32(av.w);
        }
        // --- stage B tile (k-major, contiguous n) with tf32 conversion ---
        #pragma unroll
        for (int i = 0; i < 4; i++) {
            float4 bv = *(const float4*)(Wp + (size_t)k0 * N + i * 4);
            uint4 t;
            t.x = f2tf32(bv.x); t.y = f2tf32(bv.y);
            t.z = f2tf32(bv.z); t.w = f2tf32(bv.w);
            *(uint4*)&Bs[b_row][b_nb + i * 4] = t;
        }
        __syncthreads();

        #pragma unroll
        for (int ks = 0; ks < 4; ks++) {
            const int c0 = ks * 8 + (lane & 3);
            const int r0 = lane >> 2;

            unsigned a[4][4], b[4][2];
            #pragma unroll
            for (int mi = 0; mi < 4; mi++) {
                const int m = wm + mi * 16 + r0;
                a[mi][0] = As[c0][m];
                a[mi][1] = As[c0][m + 8];
                a[mi][2] = As[c0 + 4][m];
                a[mi][3] = As[c0 + 4][m + 8];
            }
            #pragma unroll
            for (int ni = 0; ni < 4; ni++) {
                const int n = wn + ni * 8 + r0;
                b[ni][0] = Bs[c0][n];
                b[ni][1] = Bs[c0 + 4][n];
            }
            #pragma unroll
            for (int mi = 0; mi < 4; mi++)
                #pragma unroll
                for (int ni = 0; ni < 4; ni++)
                    mma_tf32(d[mi][ni], a[mi], b[ni]);
        }
        __syncthreads();
    }

    // --- epilogue: bias + store ---
    #pragma unroll
    for (int mi = 0; mi < 4; mi++) {
        const int r = row0 + wm + mi * 16 + (lane >> 2);
        #pragma unroll
        for (int ni = 0; ni < 4; ni++) {
            const int c = col0 + wn + ni * 8 + (lane & 3) * 2;
            const float b0 = bias[c], b1 = bias[c + 1];
            float2 v0 = make_float2(d[mi][ni][0] + b0, d[mi][ni][1] + b1);
            float2 v1 = make_float2(d[mi][ni][2] + b0, d[mi][ni][3] + b1);
            *(float2*)&out[(size_t)r * N + c]       = v0;
            *(float2*)&out[(size_t)(r + 8) * N + c] = v1;
        }
    }
}

// ---------------------------------------------------------------------------
// Flash-style causal attention, fp32 (unchanged this round).
// ---------------------------------------------------------------------------
#define BQ  128
#define BKV 32

__global__ __launch_bounds__(128)
void attn_kernel(const float* __restrict__ qkv, float* __restrict__ out)
{
    const int bh = blockIdx.y;
    const int b  = bh / HH;
    const int h  = bh % HH;
    const int q0 = blockIdx.x * BQ;
    const int tid = threadIdx.x;
    const int qrow = q0 + tid;

    __shared__ float Ks[BKV][DD];
    __shared__ float Vs[BKV][DD];

    float qreg[DD];
    {
        const float* qp = qkv + ((size_t)(b * TT + qrow)) * (3 * CC) + h * DD;
        #pragma unroll
        for (int d = 0; d < DD; d += 4)
            *(float4*)&qreg[d] = *(const float4*)&qp[d];
    }

    float oacc[DD];
    #pragma unroll
    for (int d = 0; d < DD; d++) oacc[d] = 0.f;
    float mmax = -CUDART_INF_F;
    float lsum = 0.f;

    const float scale = 0.125f;
    const int kv_end = q0 + BQ;

    for (int kv0 = 0; kv0 < kv_end; kv0 += BKV) {
        #pragma unroll
        for (int idx = tid; idx < BKV * DD / 4; idx += 128) {
            const int j  = idx >> 4;
            const int dd = (idx & 15) << 2;
            const float* kp = qkv + ((size_t)(b * TT + kv0 + j)) * (3 * CC) + CC + h * DD + dd;
            *(float4*)&Ks[j][dd] = *(const float4*)kp;
            *(float4*)&Vs[j][dd] = *(const float4*)(kp + CC);
        }
        __syncthreads();

        float s[BKV];
        float tilemax = -CUDART_INF_F;
        #pragma unroll
        for (int j = 0; j < BKV; j++) {
            float acc = 0.f;
            #pragma unroll
            for (int d = 0; d < DD; d += 4) {
                float4 k4 = *(const float4*)&Ks[j][d];
                acc += qreg[d + 0] * k4.x;
                acc += qreg[d + 1] * k4.y;
                acc += qreg[d + 2] * k4.z;
                acc += qreg[d + 3] * k4.w;
            }
            s[j] = (kv0 + j <= qrow) ? acc * scale : -CUDART_INF_F;
            tilemax = fmaxf(tilemax, s[j]);
        }

        const float newmax = fmaxf(mmax, tilemax);
        const float corr = __expf(mmax - newmax);
        lsum *= corr;
        #pragma unroll
        for (int d = 0; d < DD; d++) oacc[d] *= corr;

        #pragma unroll
        for (int j = 0; j < BKV; j++) {
            const float p = __expf(s[j] - newmax);
            lsum += p;
            #pragma unroll
            for (int d = 0; d < DD; d += 4) {
                float4 v4 = *(const float4*)&Vs[j][d];
                oacc[d + 0] += p * v4.x;
                oacc[d + 1] += p * v4.y;
                oacc[d + 2] += p * v4.z;
                oacc[d + 3] += p * v4.w;
            }
        }
        mmax = newmax;
        __syncthreads();
    }

    const float inv = 1.f / lsum;
    float* op = out + ((size_t)(b * TT + qrow)) * CC + h * DD;
    #pragma unroll
    for (int d = 0; d < DD; d += 4) {
        float4 r;
        r.x = oacc[d + 0] * inv;
        r.y = oacc[d + 1] * inv;
        r.z = oacc[d + 2] * inv;
        r.w = oacc[d + 3] * inv;
        *(float4*)&op[d] = r;
    }
}

// ---------------------------------------------------------------------------
// Launch
// ---------------------------------------------------------------------------
extern "C" void kernel_launch(void* const* d_in, const int* in_sizes, int n_in,
                              void* d_out, int out_size)
{
    const float* hidden = (const float*)d_in[0];   // [B,T,C]
    const float* qkv_w  = (const float*)d_in[1];   // [C, 3C]
    const float* qkv_b  = (const float*)d_in[2];   // [3C]
    const float* o_w    = (const float*)d_in[3];   // [C, C]
    const float* o_b    = (const float*)d_in[4];   // [C]
    float* out = (float*)d_out;                    // [B,T,C]

    float* qkv;  cudaGetSymbolAddress((void**)&qkv,  g_qkv);
    float* attn; cudaGetSymbolAddress((void**)&attn, g_attn);

    // 1) QKV projection: [8192,1024] @ [1024,3072] + bias -> g_qkv
    {
        dim3 grid(3 * CC / 128, BTOT / 128);
        gemm_tf32_kernel<<<grid, 256>>>(hidden, qkv_w, qkv_b, qkv, BTOT, 3 * CC, CC);
    }
    // 2) Causal multi-head attention -> g_attn
    {
        dim3 grid(TT / BQ, BB * HH);
        attn_kernel<<<grid, 128>>>(qkv, attn);
    }
    // 3) Output projection: [8192,1024] @ [1024,1024] + bias -> d_out
    {
        dim3 grid(CC / 128, BTOT / 128);
        gemm_tf32_kernel<<<grid, 256>>>(attn, o_w, o_b, out, BTOT, CC, CC);
    }
}

// round 7
// speedup vs baseline: 2.4726x; 1.9161x over previous
#include <cuda_runtime.h>
#include <math_constants.h>

#define BB 4
#define TT 2048
#define CC 1024
#define HH 16
#define DD 64
#define BTOT (BB*TT)          // 8192 rows

// Scratch (allocation-free rule: __device__ globals)
__device__ float g_qkv[(size_t)BTOT * 3 * CC];   // [B*T, 3C]
__device__ float g_attn[(size_t)BTOT * CC];      // [B*T, C]

__device__ __forceinline__ unsigned f2tf32(float x) {
    unsigned y;
    asm("cvt.rna.tf32.f32 %0, %1;" : "=r"(y) : "f"(x));
    return y;
}

__device__ __forceinline__ void mma_tf32(float d[4], const unsigned a[4], const unsigned b[2]) {
    asm volatile(
        "mma.sync.aligned.m16n8k8.row.col.f32.tf32.tf32.f32 "
        "{%0,%1,%2,%3}, {%4,%5,%6,%7}, {%8,%9}, {%0,%1,%2,%3};"
        : "+f"(d[0]), "+f"(d[1]), "+f"(d[2]), "+f"(d[3])
        : "r"(a[0]), "r"(a[1]), "r"(a[2]), "r"(a[3]), "r"(b[0]), "r"(b[1]));
}

// ---------------------------------------------------------------------------
// TF32 tensor-core GEMM + bias (unchanged from round 6)
// ---------------------------------------------------------------------------
#define SMS 136

__global__ __launch_bounds__(256)
void gemm_tf32_kernel(const float* __restrict__ A, const float* __restrict__ W,
                      const float* __restrict__ bias, float* __restrict__ out,
                      int M, int N, int K)
{
    __shared__ unsigned As[32][SMS];
    __shared__ unsigned Bs[32][SMS];

    const int tid  = threadIdx.x;
    const int lane = tid & 31;
    const int warp = tid >> 5;
    const int row0 = blockIdx.y * 128;
    const int col0 = blockIdx.x * 128;

    const int wm = (warp >> 2) * 64;
    const int wn = (warp & 3) * 32;

    const int a_row = tid >> 1;
    const int a_kb  = (tid & 1) * 16;
    const int b_row = tid >> 3;
    const int b_nb  = (tid & 7) * 16;

    const float* Ap = A + (size_t)(row0 + a_row) * K + a_kb;
    const float* Wp = W + (size_t)b_row * N + col0 + b_nb;

    float d[4][4][4];
    #pragma unroll
    for (int mi = 0; mi < 4; mi++)
        #pragma unroll
        for (int ni = 0; ni < 4; ni++)
            #pragma unroll
            for (int j = 0; j < 4; j++) d[mi][ni][j] = 0.f;

    for (int k0 = 0; k0 < K; k0 += 32) {
        #pragma unroll
        for (int i = 0; i < 4; i++) {
            float4 av = *(const float4*)(Ap + k0 + i * 4);
            As[a_kb + i * 4 + 0][a_row] = f2tf32(av.x);
            As[a_kb + i * 4 + 1][a_row] = f2tf32(av.y);
            As[a_kb + i * 4 + 2][a_row] = f2tf32(av.z);
            As[a_kb + i * 4 + 3][a_row] = f2tf32(av.w);
        }
        #pragma unroll
        for (int i = 0; i < 4; i++) {
            float4 bv = *(const float4*)(Wp + (size_t)k0 * N + i * 4);
            uint4 t;
            t.x = f2tf32(bv.x); t.y = f2tf32(bv.y);
            t.z = f2tf32(bv.z); t.w = f2tf32(bv.w);
            *(uint4*)&Bs[b_row][b_nb + i * 4] = t;
        }
        __syncthreads();

        #pragma unroll
        for (int ks = 0; ks < 4; ks++) {
            const int c0 = ks * 8 + (lane & 3);
            const int r0 = lane >> 2;

            unsigned a[4][4], b[4][2];
            #pragma unroll
            for (int mi = 0; mi < 4; mi++) {
                const int m = wm + mi * 16 + r0;
                a[mi][0] = As[c0][m];
                a[mi][1] = As[c0][m + 8];
                a[mi][2] = As[c0 + 4][m];
                a[mi][3] = As[c0 + 4][m + 8];
            }
            #pragma unroll
            for (int ni = 0; ni < 4; ni++) {
                const int n = wn + ni * 8 + r0;
                b[ni][0] = Bs[c0][n];
                b[ni][1] = Bs[c0 + 4][n];
            }
            #pragma unroll
            for (int mi = 0; mi < 4; mi++)
                #pragma unroll
                for (int ni = 0; ni < 4; ni++)
                    mma_tf32(d[mi][ni], a[mi], b[ni]);
        }
        __syncthreads();
    }

    #pragma unroll
    for (int mi = 0; mi < 4; mi++) {
        const int r = row0 + wm + mi * 16 + (lane >> 2);
        #pragma unroll
        for (int ni = 0; ni < 4; ni++) {
            const int c = col0 + wn + ni * 8 + (lane & 3) * 2;
            const float b0 = bias[c], b1 = bias[c + 1];
            float2 v0 = make_float2(d[mi][ni][0] + b0, d[mi][ni][1] + b1);
            float2 v1 = make_float2(d[mi][ni][2] + b0, d[mi][ni][3] + b1);
            *(float2*)&out[(size_t)r * N + c]       = v0;
            *(float2*)&out[(size_t)(r + 8) * N + c] = v1;
        }
    }
}

// ---------------------------------------------------------------------------
// Tensor-core flash attention (tf32 MMA, fp32 softmax).
// Block = one (b,h) x 64 q-rows. 4 warps, each owns 16 q-rows.
// KV tiles of 64. K smem stride 68, V stride 72 (conflict-free b-frag reads).
// Q staged into the V buffer first (released after frags are in registers).
// ---------------------------------------------------------------------------
#define KSTR 68
#define VSTR 72

__global__ __launch_bounds__(128)
void attn_tc_kernel(const float* __restrict__ qkv, float* __restrict__ out)
{
    __shared__ unsigned Ks[64 * KSTR];
    __shared__ unsigned VQ[64 * VSTR];   // V tile; Q staged here first (stride KSTR)

    const int bh  = blockIdx.y;
    const int b   = bh >> 4;
    const int h   = bh & 15;
    const int q0  = blockIdx.x * 64;
    const int tid = threadIdx.x;
    const int lane = tid & 31;
    const int warp = tid >> 5;
    const int g = lane >> 2;
    const int t = lane & 3;

    const size_t rstr = 3 * CC;

    // ---- stage Q (pre-scaled by 1/8 = exact, tf32) into VQ, stride KSTR ----
    {
        const int row = tid >> 1;
        const int cb  = (tid & 1) * 32;
        const float* qp = qkv + ((size_t)(b * TT + q0 + row)) * rstr + h * DD + cb;
        #pragma unroll
        for (int i = 0; i < 8; i++) {
            float4 v = *(const float4*)(qp + i * 4);
            unsigned* dst = &VQ[row * KSTR + cb + i * 4];
            dst[0] = f2tf32(v.x * 0.125f);
            dst[1] = f2tf32(v.y * 0.125f);
            dst[2] = f2tf32(v.z * 0.125f);
            dst[3] = f2tf32(v.w * 0.125f);
        }
    }
    __syncthreads();

    // ---- Q fragments (kept in registers for the whole kernel) ----
    unsigned qa[8][4];
    {
        const int r = warp * 16 + g;
        #pragma unroll
        for (int kk = 0; kk < 8; kk++) {
            qa[kk][0] = VQ[r * KSTR + kk * 8 + t];
            qa[kk][1] = VQ[(r + 8) * KSTR + kk * 8 + t];
            qa[kk][2] = VQ[r * KSTR + kk * 8 + t + 4];
            qa[kk][3] = VQ[(r + 8) * KSTR + kk * 8 + t + 4];
        }
    }
    __syncthreads();   // Q buffer free -> V can overwrite

    float o[8][4];
    #pragma unroll
    for (int nt = 0; nt < 8; nt++)
        #pragma unroll
        for (int j = 0; j < 4; j++) o[nt][j] = 0.f;
    float m0 = -CUDART_INF_F, m1 = -CUDART_INF_F;
    float l0 = 0.f, l1 = 0.f;

    const int r_lo = q0 + warp * 16 + g;
    const int r_hi = r_lo + 8;

    for (int kv0 = 0; kv0 < q0 + 64; kv0 += 64) {
        // ---- stage K (stride KSTR) and V (stride VSTR), tf32 ----
        {
            const int row = tid >> 1;
            const int cb  = (tid & 1) * 32;
            const float* kp = qkv + ((size_t)(b * TT + kv0 + row)) * rstr + CC + h * DD + cb;
            #pragma unroll
            for (int i = 0; i < 8; i++) {
                float4 kv4 = *(const float4*)(kp + i * 4);
                unsigned* kd = &Ks[row * KSTR + cb + i * 4];
                kd[0] = f2tf32(kv4.x); kd[1] = f2tf32(kv4.y);
                kd[2] = f2tf32(kv4.z); kd[3] = f2tf32(kv4.w);
                float4 vv4 = *(const float4*)(kp + CC + i * 4);
                unsigned* vd = &VQ[row * VSTR + cb + i * 4];
                vd[0] = f2tf32(vv4.x); vd[1] = f2tf32(vv4.y);
                vd[2] = f2tf32(vv4.z); vd[3] = f2tf32(vv4.w);
            }
        }
        __syncthreads();

        // ---- S = Q K^T  (16 x 64 per warp) ----
        float s[8][4];
        #pragma unroll
        for (int nt = 0; nt < 8; nt++) {
            s[nt][0] = 0.f; s[nt][1] = 0.f; s[nt][2] = 0.f; s[nt][3] = 0.f;
            #pragma unroll
            for (int kk = 0; kk < 8; kk++) {
                unsigned bfr[2];
                bfr[0] = Ks[(nt * 8 + g) * KSTR + kk * 8 + t];
                bfr[1] = Ks[(nt * 8 + g) * KSTR + kk * 8 + t + 4];
                mma_tf32(s[nt], qa[kk], bfr);
            }
        }

        // ---- causal mask (only the diagonal tile) ----
        if (kv0 + 64 > q0) {
            #pragma unroll
            for (int nt = 0; nt < 8; nt++) {
                const int c0col = kv0 + nt * 8 + 2 * t;
                if (c0col     > r_lo) s[nt][0] = -CUDART_INF_F;
                if (c0col + 1 > r_lo) s[nt][1] = -CUDART_INF_F;
                if (c0col     > r_hi) s[nt][2] = -CUDART_INF_F;
                if (c0col + 1 > r_hi) s[nt][3] = -CUDART_INF_F;
            }
        }

        // ---- online softmax ----
        float mx0 = -CUDART_INF_F, mx1 = -CUDART_INF_F;
        #pragma unroll
        for (int nt = 0; nt < 8; nt++) {
            mx0 = fmaxf(mx0, fmaxf(s[nt][0], s[nt][1]));
            mx1 = fmaxf(mx1, fmaxf(s[nt][2], s[nt][3]));
        }
        mx0 = fmaxf(mx0, __shfl_xor_sync(0xffffffffu, mx0, 1));
        mx0 = fmaxf(mx0, __shfl_xor_sync(0xffffffffu, mx0, 2));
        mx1 = fmaxf(mx1, __shfl_xor_sync(0xffffffffu, mx1, 1));
        mx1 = fmaxf(mx1, __shfl_xor_sync(0xffffffffu, mx1, 2));

        const float M0 = fmaxf(m0, mx0), M1 = fmaxf(m1, mx1);
        const float cor0 = __expf(m0 - M0), cor1 = __expf(m1 - M1);
        l0 *= cor0; l1 *= cor1;
        #pragma unroll
        for (int nt = 0; nt < 8; nt++) {
            o[nt][0] *= cor0; o[nt][1] *= cor0;
            o[nt][2] *= cor1; o[nt][3] *= cor1;
        }
        m0 = M0; m1 = M1;

        #pragma unroll
        for (int nt = 0; nt < 8; nt++) {
            s[nt][0] = __expf(s[nt][0] - M0);
            s[nt][1] = __expf(s[nt][1] - M0);
            s[nt][2] = __expf(s[nt][2] - M1);
            s[nt][3] = __expf(s[nt][3] - M1);
            l0 += s[nt][0] + s[nt][1];
            l1 += s[nt][2] + s[nt][3];
        }

        // ---- O += P V : C-frag -> A-frag via quad shfl, then MMA ----
        const int srcA = (lane & 28) | (t >> 1);
        const int srcB = srcA + 2;
        const bool hi = (t & 1);
        #pragma unroll
        for (int kk = 0; kk < 8; kk++) {
            const float x0 = __shfl_sync(0xffffffffu, s[kk][0], srcA);
            const float x1 = __shfl_sync(0xffffffffu, s[kk][1], srcA);
            const float x2 = __shfl_sync(0xffffffffu, s[kk][2], srcA);
            const float x3 = __shfl_sync(0xffffffffu, s[kk][3], srcA);
            const float y0 = __shfl_sync(0xffffffffu, s[kk][0], srcB);
            const float y1 = __shfl_sync(0xffffffffu, s[kk][1], srcB);
            const float y2 = __shfl_sync(0xffffffffu, s[kk][2], srcB);
            const float y3 = __shfl_sync(0xffffffffu, s[kk][3], srcB);
            unsigned pa[4];
            pa[0] = f2tf32(hi ? x1 : x0);
            pa[1] = f2tf32(hi ? x3 : x2);
            pa[2] = f2tf32(hi ? y1 : y0);
            pa[3] = f2tf32(hi ? y3 : y2);
            #pragma unroll
            for (int nt2 = 0; nt2 < 8; nt2++) {
                unsigned bfr[2];
                bfr[0] = VQ[(kk * 8 + t) * VSTR + nt2 * 8 + g];
                bfr[1] = VQ[(kk * 8 + t + 4) * VSTR + nt2 * 8 + g];
                mma_tf32(o[nt2], pa, bfr);
            }
        }
        __syncthreads();
    }

    // ---- finalize: reduce l across quad, normalize, store ----
    l0 += __shfl_xor_sync(0xffffffffu, l0, 1);
    l0 += __shfl_xor_sync(0xffffffffu, l0, 2);
    l1 += __shfl_xor_sync(0xffffffffu, l1, 1);
    l1 += __shfl_xor_sync(0xffffffffu, l1, 2);
    const float inv0 = 1.f / l0, inv1 = 1.f / l1;

    float* op_lo = out + ((size_t)(b * TT + r_lo)) * CC + h * DD;
    float* op_hi = out + ((size_t)(b * TT + r_hi)) * CC + h * DD;
    #pragma unroll
    for (int nt2 = 0; nt2 < 8; nt2++) {
        const int c = nt2 * 8 + 2 * t;
        *(float2*)&op_lo[c] = make_float2(o[nt2][0] * inv0, o[nt2][1] * inv0);
        *(float2*)&op_hi[c] = make_float2(o[nt2][2] * inv1, o[nt2][3] * inv1);
    }
}

// ---------------------------------------------------------------------------
// Launch
// ---------------------------------------------------------------------------
extern "C" void kernel_launch(void* const* d_in, const int* in_sizes, int n_in,
                              void* d_out, int out_size)
{
    const float* hidden = (const float*)d_in[0];   // [B,T,C]
    const float* qkv_w  = (const float*)d_in[1];   // [C, 3C]
    const float* qkv_b  = (const float*)d_in[2];   // [3C]
    const float* o_w    = (const float*)d_in[3];   // [C, C]
    const float* o_b    = (const float*)d_in[4];   // [C]
    float* out = (float*)d_out;                    // [B,T,C]

    float* qkv;  cudaGetSymbolAddress((void**)&qkv,  g_qkv);
    float* attn; cudaGetSymbolAddress((void**)&attn, g_attn);

    // 1) QKV projection
    {
        dim3 grid(3 * CC / 128, BTOT / 128);
        gemm_tf32_kernel<<<grid, 256>>>(hidden, qkv_w, qkv_b, qkv, BTOT, 3 * CC, CC);
    }
    // 2) Causal multi-head attention (tensor cores)
    {
        dim3 grid(TT / 64, BB * HH);
        attn_tc_kernel<<<grid, 128>>>(qkv, attn);
    }
    // 3) Output projection
    {
        dim3 grid(CC / 128, BTOT / 128);
        gemm_tf32_kernel<<<grid, 256>>>(attn, o_w, o_b, out, BTOT, CC, CC);
    }
}

// round 10
// speedup vs baseline: 3.0647x; 1.2395x over previous
#include <cuda_runtime.h>
#include <math_constants.h>

#define BB 4
#define TT 2048
#define CC 1024
#define HH 16
#define DD 64
#define BTOT (BB*TT)          // 8192 rows

// Scratch (allocation-free rule: __device__ globals)
__device__ float g_qkv[(size_t)BTOT * 3 * CC];   // [B*T, 3C]  (tf32-rounded values)
__device__ float g_attn[(size_t)BTOT * CC];      // [B*T, C]   (tf32-rounded values)
__device__ float g_x [(size_t)BTOT * CC];        // hidden, tf32-rounded
__device__ float g_w1[(size_t)CC * 3 * CC];      // qkv_w, tf32-rounded
__device__ float g_w2[(size_t)CC * CC];          // o_w, tf32-rounded

__device__ __forceinline__ unsigned f2tf32(float x) {
    unsigned y;
    asm("cvt.rna.tf32.f32 %0, %1;" : "=r"(y) : "f"(x));
    return y;
}

__device__ __forceinline__ void mma_tf32(float d[4], const unsigned a[4], const unsigned b[2]) {
    asm volatile(
        "mma.sync.aligned.m16n8k8.row.col.f32.tf32.tf32.f32 "
        "{%0,%1,%2,%3}, {%4,%5,%6,%7}, {%8,%9}, {%0,%1,%2,%3};"
        : "+f"(d[0]), "+f"(d[1]), "+f"(d[2]), "+f"(d[3])
        : "r"(a[0]), "r"(a[1]), "r"(a[2]), "r"(a[3]), "r"(b[0]), "r"(b[1]));
}

__device__ __forceinline__ void cp_async16(void* smem_dst, const void* gsrc) {
    unsigned sa = (unsigned)__cvta_generic_to_shared(smem_dst);
    asm volatile("cp.async.ca.shared.global [%0], [%1], 16;" :: "r"(sa), "l"(gsrc));
}

// ---------------------------------------------------------------------------
// Pre-pass: fp32 -> tf32-rounded fp32 (vectorized)
// ---------------------------------------------------------------------------
__global__ void cvt_tf32_kernel(const float4* __restrict__ in, float4* __restrict__ out, int n4)
{
    int i = blockIdx.x * blockDim.x + threadIdx.x;
    if (i < n4) {
        float4 v = in[i];
        uint4 r;
        r.x = f2tf32(v.x); r.y = f2tf32(v.y);
        r.z = f2tf32(v.z); r.w = f2tf32(v.w);
        *(uint4*)&out[i] = r;
    }
}

// ---------------------------------------------------------------------------
// cp.async double-buffered TF32 GEMM + bias. Inputs pre-converted to tf32.
// out[M,N] = A[M,K] @ W[K,N] + bias[N]. 128x128 block tile, BK=16,
// 256 threads (8 warps, 2x4 grid, 64x32 warp tile).
// A smem row-major stride 20 (banks 4*perm(g)+t), B k-major stride 136 (8t+g).
// ---------------------------------------------------------------------------
#define ASTR 20
#define BSTR 136

template<bool ROUND>
__global__ __launch_bounds__(256)
void gemm_tf32_pipe(const float* __restrict__ A, const float* __restrict__ W,
                    const float* __restrict__ bias, float* __restrict__ out,
                    int M, int N, int K)
{
    __shared__ unsigned As[2][128 * ASTR];
    __shared__ unsigned Bs[2][16 * BSTR];

    const int tid  = threadIdx.x;
    const int lane = tid & 31;
    const int warp = tid >> 5;
    const int g = lane >> 2;
    const int t = lane & 3;
    const int row0 = blockIdx.y * 128;
    const int col0 = blockIdx.x * 128;

    const int wm = (warp >> 2) * 64;
    const int wn = (warp & 3) * 32;

    const int ntiles = K >> 4;

    // stage loader: 2 A chunks + 2 B chunks of 16B per thread
    const int a_r0 = tid >> 2,  a_c = (tid & 3) * 4;          // A: rows 0..63 (+64), col chunk
    const int b_r0 = tid >> 5,  b_c = (tid & 31) * 4;         // B: rows 0..7 (+8)

    #define LOAD_STAGE(kt, slot) do {                                              \
        const int k0_ = (kt) << 4;                                                 \
        cp_async16(&As[slot][(a_r0)      * ASTR + a_c],                            \
                   A + (size_t)(row0 + a_r0)      * K + k0_ + a_c);                \
        cp_async16(&As[slot][(a_r0 + 64) * ASTR + a_c],                            \
                   A + (size_t)(row0 + a_r0 + 64) * K + k0_ + a_c);                \
        cp_async16(&Bs[slot][(b_r0)     * BSTR + b_c],                             \
                   W + (size_t)(k0_ + b_r0)     * N + col0 + b_c);                 \
        cp_async16(&Bs[slot][(b_r0 + 8) * BSTR + b_c],                             \
                   W + (size_t)(k0_ + b_r0 + 8) * N + col0 + b_c);                 \
        asm volatile("cp.async.commit_group;" ::: "memory");                       \
    } while (0)

    float d[4][4][4];
    #pragma unroll
    for (int mi = 0; mi < 4; mi++)
        #pragma unroll
        for (int ni = 0; ni < 4; ni++)
            #pragma unroll
            for (int j = 0; j < 4; j++) d[mi][ni][j] = 0.f;

    LOAD_STAGE(0, 0);

    for (int kt = 0; kt < ntiles; kt++) {
        asm volatile("cp.async.wait_group 0;" ::: "memory");
        __syncthreads();
        if (kt + 1 < ntiles) {
            if ((kt + 1) & 1) LOAD_STAGE(kt + 1, 1);
            else              LOAD_STAGE(kt + 1, 0);
        }

        const unsigned* as = As[kt & 1];
        const unsigned* bs = Bs[kt & 1];

        #pragma unroll
        for (int ks = 0; ks < 2; ks++) {
            const int c0 = ks * 8 + t;
            unsigned a[4][4], b[4][2];
            #pragma unroll
            for (int mi = 0; mi < 4; mi++) {
                const int m = wm + mi * 16 + g;
                a[mi][0] = as[m * ASTR + c0];
                a[mi][1] = as[(m + 8) * ASTR + c0];
                a[mi][2] = as[m * ASTR + c0 + 4];
                a[mi][3] = as[(m + 8) * ASTR + c0 + 4];
            }
            #pragma unroll
            for (int ni = 0; ni < 4; ni++) {
                const int n = wn + ni * 8 + g;
                b[ni][0] = bs[c0 * BSTR + n];
                b[ni][1] = bs[(c0 + 4) * BSTR + n];
            }
            #pragma unroll
            for (int mi = 0; mi < 4; mi++)
                #pragma unroll
                for (int ni = 0; ni < 4; ni++)
                    mma_tf32(d[mi][ni], a[mi], b[ni]);
        }
    }

    // epilogue: bias + store (optionally tf32-rounded)
    #pragma unroll
    for (int mi = 0; mi < 4; mi++) {
        const int r = row0 + wm + mi * 16 + g;
        #pragma unroll
        for (int ni = 0; ni < 4; ni++) {
            const int c = col0 + wn + ni * 8 + 2 * t;
            const float b0 = bias[c], b1 = bias[c + 1];
            float v00 = d[mi][ni][0] + b0, v01 = d[mi][ni][1] + b1;
            float v10 = d[mi][ni][2] + b0, v11 = d[mi][ni][3] + b1;
            if (ROUND) {
                v00 = __uint_as_float(f2tf32(v00));
                v01 = __uint_as_float(f2tf32(v01));
                v10 = __uint_as_float(f2tf32(v10));
                v11 = __uint_as_float(f2tf32(v11));
            }
            *(float2*)&out[(size_t)r * N + c]       = make_float2(v00, v01);
            *(float2*)&out[(size_t)(r + 8) * N + c] = make_float2(v10, v11);
        }
    }
    #undef LOAD_STAGE
}

// ---------------------------------------------------------------------------
// Tensor-core flash attention (tf32 MMA, fp32 softmax).
// qkv values are already tf32-rounded -> staging needs no cvt.
// Output stored tf32-rounded (feeds cvt-free GEMM2).
// ---------------------------------------------------------------------------
#define KSTR 68
#define VSTR 72

__global__ __launch_bounds__(128)
void attn_tc_kernel(const float* __restrict__ qkv, float* __restrict__ out)
{
    __shared__ unsigned Ks[64 * KSTR];
    __shared__ unsigned VQ[64 * VSTR];   // V tile; Q staged here first (stride KSTR)

    const int bh  = blockIdx.y;
    const int b   = bh >> 4;
    const int h   = bh & 15;
    const int q0  = (gridDim.x - 1 - blockIdx.x) * 64;   // longest blocks first
    const int tid = threadIdx.x;
    const int lane = tid & 31;
    const int warp = tid >> 5;
    const int g = lane >> 2;
    const int t = lane & 3;

    const size_t rstr = 3 * CC;

    // ---- stage Q (x 1/8 exact) into VQ, stride KSTR ----
    {
        const int row = tid >> 1;
        const int cb  = (tid & 1) * 32;
        const float* qp = qkv + ((size_t)(b * TT + q0 + row)) * rstr + h * DD + cb;
        #pragma unroll
        for (int i = 0; i < 8; i++) {
            float4 v = *(const float4*)(qp + i * 4);
            unsigned* dst = &VQ[row * KSTR + cb + i * 4];
            dst[0] = __float_as_uint(v.x * 0.125f);
            dst[1] = __float_as_uint(v.y * 0.125f);
            dst[2] = __float_as_uint(v.z * 0.125f);
            dst[3] = __float_as_uint(v.w * 0.125f);
        }
    }
    __syncthreads();

    unsigned qa[8][4];
    {
        const int r = warp * 16 + g;
        #pragma unroll
        for (int kk = 0; kk < 8; kk++) {
            qa[kk][0] = VQ[r * KSTR + kk * 8 + t];
            qa[kk][1] = VQ[(r + 8) * KSTR + kk * 8 + t];
            qa[kk][2] = VQ[r * KSTR + kk * 8 + t + 4];
            qa[kk][3] = VQ[(r + 8) * KSTR + kk * 8 + t + 4];
        }
    }
    __syncthreads();

    float o[8][4];
    #pragma unroll
    for (int nt = 0; nt < 8; nt++)
        #pragma unroll
        for (int j = 0; j < 4; j++) o[nt][j] = 0.f;
    float m0 = -CUDART_INF_F, m1 = -CUDART_INF_F;
    float l0 = 0.f, l1 = 0.f;

    const int r_lo = q0 + warp * 16 + g;
    const int r_hi = r_lo + 8;

    for (int kv0 = 0; kv0 < q0 + 64; kv0 += 64) {
        {
            const int row = tid >> 1;
            const int cb  = (tid & 1) * 32;
            const float* kp = qkv + ((size_t)(b * TT + kv0 + row)) * rstr + CC + h * DD + cb;
            #pragma unroll
            for (int i = 0; i < 8; i++) {
                float4 kv4 = *(const float4*)(kp + i * 4);
                unsigned* kd = &Ks[row * KSTR + cb + i * 4];
                kd[0] = __float_as_uint(kv4.x); kd[1] = __float_as_uint(kv4.y);
                kd[2] = __float_as_uint(kv4.z); kd[3] = __float_as_uint(kv4.w);
                float4 vv4 = *(const float4*)(kp + CC + i * 4);
                unsigned* vd = &VQ[row * VSTR + cb + i * 4];
                vd[0] = __float_as_uint(vv4.x); vd[1] = __float_as_uint(vv4.y);
                vd[2] = __float_as_uint(vv4.z); vd[3] = __float_as_uint(vv4.w);
            }
        }
        __syncthreads();

        // ---- S = Q K^T ----
        float s[8][4];
        #pragma unroll
        for (int nt = 0; nt < 8; nt++) {
            s[nt][0] = 0.f; s[nt][1] = 0.f; s[nt][2] = 0.f; s[nt][3] = 0.f;
            #pragma unroll
            for (int kk = 0; kk < 8; kk++) {
                unsigned bfr[2];
                bfr[0] = Ks[(nt * 8 + g) * KSTR + kk * 8 + t];
                bfr[1] = Ks[(nt * 8 + g) * KSTR + kk * 8 + t + 4];
                mma_tf32(s[nt], qa[kk], bfr);
            }
        }

        // ---- causal mask (diagonal tile only) ----
        if (kv0 + 64 > q0) {
            #pragma unroll
            for (int nt = 0; nt < 8; nt++) {
                const int c0col = kv0 + nt * 8 + 2 * t;
                if (c0col     > r_lo) s[nt][0] = -CUDART_INF_F;
                if (c0col + 1 > r_lo) s[nt][1] = -CUDART_INF_F;
                if (c0col     > r_hi) s[nt][2] = -CUDART_INF_F;
                if (c0col + 1 > r_hi) s[nt][3] = -CUDART_INF_F;
            }
        }

        // ---- online softmax ----
        float mx0 = -CUDART_INF_F, mx1 = -CUDART_INF_F;
        #pragma unroll
        for (int nt = 0; nt < 8; nt++) {
            mx0 = fmaxf(mx0, fmaxf(s[nt][0], s[nt][1]));
            mx1 = fmaxf(mx1, fmaxf(s[nt][2], s[nt][3]));
        }
        mx0 = fmaxf(mx0, __shfl_xor_sync(0xffffffffu, mx0, 1));
        mx0 = fmaxf(mx0, __shfl_xor_sync(0xffffffffu, mx0, 2));
        mx1 = fmaxf(mx1, __shfl_xor_sync(0xffffffffu, mx1, 1));
        mx1 = fmaxf(mx1, __shfl_xor_sync(0xffffffffu, mx1, 2));

        const float M0 = fmaxf(m0, mx0), M1 = fmaxf(m1, mx1);
        const float cor0 = __expf(m0 - M0), cor1 = __expf(m1 - M1);
        l0 *= cor0; l1 *= cor1;
        #pragma unroll
        for (int nt = 0; nt < 8; nt++) {
            o[nt][0] *= cor0; o[nt][1] *= cor0;
            o[nt][2] *= cor1; o[nt][3] *= cor1;
        }
        m0 = M0; m1 = M1;

        #pragma unroll
        for (int nt = 0; nt < 8; nt++) {
            s[nt][0] = __expf(s[nt][0] - M0);
            s[nt][1] = __expf(s[nt][1] - M0);
            s[nt][2] = __expf(s[nt][2] - M1);
            s[nt][3] = __expf(s[nt][3] - M1);
            l0 += s[nt][0] + s[nt][1];
            l1 += s[nt][2] + s[nt][3];
        }

        // ---- O += P V : C-frag -> A-frag via quad shfl, then MMA ----
        const int srcA = (lane & 28) | (t >> 1);
        const int srcB = srcA + 2;
        const bool hi = (t & 1);
        #pragma unroll
        for (int kk = 0; kk < 8; kk++) {
            const float x0 = __shfl_sync(0xffffffffu, s[kk][0], srcA);
            const float x1 = __shfl_sync(0xffffffffu, s[kk][1], srcA);
            const float x2 = __shfl_sync(0xffffffffu, s[kk][2], srcA);
            const float x3 = __shfl_sync(0xffffffffu, s[kk][3], srcA);
            const float y0 = __shfl_sync(0xffffffffu, s[kk][0], srcB);
            const float y1 = __shfl_sync(0xffffffffu, s[kk][1], srcB);
            const float y2 = __shfl_sync(0xffffffffu, s[kk][2], srcB);
            const float y3 = __shfl_sync(0xffffffffu, s[kk][3], srcB);
            unsigned pa[4];
            pa[0] = f2tf32(hi ? x1 : x0);
            pa[1] = f2tf32(hi ? x3 : x2);
            pa[2] = f2tf32(hi ? y1 : y0);
            pa[3] = f2tf32(hi ? y3 : y2);
            #pragma unroll
            for (int nt2 = 0; nt2 < 8; nt2++) {
                unsigned bfr[2];
                bfr[0] = VQ[(kk * 8 + t) * VSTR + nt2 * 8 + g];
                bfr[1] = VQ[(kk * 8 + t + 4) * VSTR + nt2 * 8 + g];
                mma_tf32(o[nt2], pa, bfr);
            }
        }
        __syncthreads();
    }

    l0 += __shfl_xor_sync(0xffffffffu, l0, 1);
    l0 += __shfl_xor_sync(0xffffffffu, l0, 2);
    l1 += __shfl_xor_sync(0xffffffffu, l1, 1);
    l1 += __shfl_xor_sync(0xffffffffu, l1, 2);
    const float inv0 = 1.f / l0, inv1 = 1.f / l1;

    float* op_lo = out + ((size_t)(b * TT + r_lo)) * CC + h * DD;
    float* op_hi = out + ((size_t)(b * TT + r_hi)) * CC + h * DD;
    #pragma unroll
    for (int nt2 = 0; nt2 < 8; nt2++) {
        const int c = nt2 * 8 + 2 * t;
        float2 vlo = make_float2(__uint_as_float(f2tf32(o[nt2][0] * inv0)),
                                 __uint_as_float(f2tf32(o[nt2][1] * inv0)));
        float2 vhi = make_float2(__uint_as_float(f2tf32(o[nt2][2] * inv1)),
                                 __uint_as_float(f2tf32(o[nt2][3] * inv1)));
        *(float2*)&op_lo[c] = vlo;
        *(float2*)&op_hi[c] = vhi;
    }
}

// ---------------------------------------------------------------------------
// Launch
// ---------------------------------------------------------------------------
extern "C" void kernel_launch(void* const* d_in, const int* in_sizes, int n_in,
                              void* d_out, int out_size)
{
    const float* hidden = (const float*)d_in[0];   // [B,T,C]
    const float* qkv_w  = (const float*)d_in[1];   // [C, 3C]
    const float* qkv_b  = (const float*)d_in[2];   // [3C]
    const float* o_w    = (const float*)d_in[3];   // [C, C]
    const float* o_b    = (const float*)d_in[4];   // [C]
    float* out = (float*)d_out;                    // [B,T,C]

    float *qkv, *attn, *x, *w1, *w2;
    cudaGetSymbolAddress((void**)&qkv,  g_qkv);
    cudaGetSymbolAddress((void**)&attn, g_attn);
    cudaGetSymbolAddress((void**)&x,    g_x);
    cudaGetSymbolAddress((void**)&w1,   g_w1);
    cudaGetSymbolAddress((void**)&w2,   g_w2);

    // 0) pre-convert operands to tf32
    {
        int n4;
        n4 = BTOT * CC / 4;
        cvt_tf32_kernel<<<(n4 + 255) / 256, 256>>>((const float4*)hidden, (float4*)x, n4);
        n4 = CC * 3 * CC / 4;
        cvt_tf32_kernel<<<(n4 + 255) / 256, 256>>>((const float4*)qkv_w, (float4*)w1, n4);
        n4 = CC * CC / 4;
        cvt_tf32_kernel<<<(n4 + 255) / 256, 256>>>((const float4*)o_w, (float4*)w2, n4);
    }
    // 1) QKV projection (output tf32-rounded for the attention kernel)
    {
        dim3 grid(3 * CC / 128, BTOT / 128);
        gemm_tf32_pipe<true><<<grid, 256>>>(x, w1, qkv_b, qkv, BTOT, 3 * CC, CC);
    }
    // 2) Causal multi-head attention (tensor cores; output tf32-rounded)
    {
        dim3 grid(TT / 64, BB * HH);
        attn_tc_kernel<<<grid, 128>>>(qkv, attn);
    }
    // 3) Output projection (full fp32 output)
    {
        dim3 grid(CC / 128, BTOT / 128);
        gemm_tf32_pipe<false><<<grid, 256>>>(attn, w2, o_b, out, BTOT, CC, CC);
    }
}

// round 14
// speedup vs baseline: 3.8630x; 1.2605x over previous
#include <cuda_runtime.h>
#include <math_constants.h>

#define BB 4
#define TT 2048
#define CC 1024
#define HH 16
#define DD 64
#define BTOT (BB*TT)          // 8192 rows

// Scratch (allocation-free rule: __device__ globals)
__device__ float g_qkv[(size_t)BTOT * 3 * CC];   // [B*T, 3C]  (tf32-rounded values)
__device__ float g_attn[(size_t)BTOT * CC];      // [B*T, C]   (tf32-rounded values)
__device__ float g_x [(size_t)BTOT * CC];        // hidden, tf32-rounded
__device__ float g_w1[(size_t)CC * 3 * CC];      // qkv_w, tf32-rounded
__device__ float g_w2[(size_t)CC * CC];          // o_w, tf32-rounded

__device__ __forceinline__ unsigned f2tf32(float x) {
    unsigned y;
    asm("cvt.rna.tf32.f32 %0, %1;" : "=r"(y) : "f"(x));
    return y;
}

__device__ __forceinline__ void mma_tf32(float d[4], const unsigned a[4], const unsigned b[2]) {
    asm volatile(
        "mma.sync.aligned.m16n8k8.row.col.f32.tf32.tf32.f32 "
        "{%0,%1,%2,%3}, {%4,%5,%6,%7}, {%8,%9}, {%0,%1,%2,%3};"
        : "+f"(d[0]), "+f"(d[1]), "+f"(d[2]), "+f"(d[3])
        : "r"(a[0]), "r"(a[1]), "r"(a[2]), "r"(a[3]), "r"(b[0]), "r"(b[1]));
}

__device__ __forceinline__ void cp_async16(void* smem_dst, const void* gsrc) {
    unsigned sa = (unsigned)__cvta_generic_to_shared(smem_dst);
    asm volatile("cp.async.ca.shared.global [%0], [%1], 16;" :: "r"(sa), "l"(gsrc));
}

// ---------------------------------------------------------------------------
// Pre-pass: fp32 -> tf32-rounded fp32 (vectorized)
// ---------------------------------------------------------------------------
__global__ void cvt_tf32_kernel(const float4* __restrict__ in, float4* __restrict__ out, int n4)
{
    int i = blockIdx.x * blockDim.x + threadIdx.x;
    if (i < n4) {
        float4 v = in[i];
        uint4 r;
        r.x = f2tf32(v.x); r.y = f2tf32(v.y);
        r.z = f2tf32(v.z); r.w = f2tf32(v.w);
        *(uint4*)&out[i] = r;
    }
}

// ---------------------------------------------------------------------------
// cp.async double-buffered TF32 GEMM + bias (unchanged from round 10).
// ---------------------------------------------------------------------------
#define ASTR 20
#define BSTR 136

template<bool ROUND>
__global__ __launch_bounds__(256)
void gemm_tf32_pipe(const float* __restrict__ A, const float* __restrict__ W,
                    const float* __restrict__ bias, float* __restrict__ out,
                    int M, int N, int K)
{
    __shared__ unsigned As[2][128 * ASTR];
    __shared__ unsigned Bs[2][16 * BSTR];

    const int tid  = threadIdx.x;
    const int lane = tid & 31;
    const int warp = tid >> 5;
    const int g = lane >> 2;
    const int t = lane & 3;
    const int row0 = blockIdx.y * 128;
    const int col0 = blockIdx.x * 128;

    const int wm = (warp >> 2) * 64;
    const int wn = (warp & 3) * 32;

    const int ntiles = K >> 4;

    const int a_r0 = tid >> 2,  a_c = (tid & 3) * 4;
    const int b_r0 = tid >> 5,  b_c = (tid & 31) * 4;

    #define LOAD_STAGE(kt, slot) do {                                              \
        const int k0_ = (kt) << 4;                                                 \
        cp_async16(&As[slot][(a_r0)      * ASTR + a_c],                            \
                   A + (size_t)(row0 + a_r0)      * K + k0_ + a_c);                \
        cp_async16(&As[slot][(a_r0 + 64) * ASTR + a_c],                            \
                   A + (size_t)(row0 + a_r0 + 64) * K + k0_ + a_c);                \
        cp_async16(&Bs[slot][(b_r0)     * BSTR + b_c],                             \
                   W + (size_t)(k0_ + b_r0)     * N + col0 + b_c);                 \
        cp_async16(&Bs[slot][(b_r0 + 8) * BSTR + b_c],                             \
                   W + (size_t)(k0_ + b_r0 + 8) * N + col0 + b_c);                 \
        asm volatile("cp.async.commit_group;" ::: "memory");                       \
    } while (0)

    float d[4][4][4];
    #pragma unroll
    for (int mi = 0; mi < 4; mi++)
        #pragma unroll
        for (int ni = 0; ni < 4; ni++)
            #pragma unroll
            for (int j = 0; j < 4; j++) d[mi][ni][j] = 0.f;

    LOAD_STAGE(0, 0);

    for (int kt = 0; kt < ntiles; kt++) {
        asm volatile("cp.async.wait_group 0;" ::: "memory");
        __syncthreads();
        if (kt + 1 < ntiles) {
            if ((kt + 1) & 1) LOAD_STAGE(kt + 1, 1);
            else              LOAD_STAGE(kt + 1, 0);
        }

        const unsigned* as = As[kt & 1];
        const unsigned* bs = Bs[kt & 1];

        #pragma unroll
        for (int ks = 0; ks < 2; ks++) {
            const int c0 = ks * 8 + t;
            unsigned a[4][4], b[4][2];
            #pragma unroll
            for (int mi = 0; mi < 4; mi++) {
                const int m = wm + mi * 16 + g;
                a[mi][0] = as[m * ASTR + c0];
                a[mi][1] = as[(m + 8) * ASTR + c0];
                a[mi][2] = as[m * ASTR + c0 + 4];
                a[mi][3] = as[(m + 8) * ASTR + c0 + 4];
            }
            #pragma unroll
            for (int ni = 0; ni < 4; ni++) {
                const int n = wn + ni * 8 + g;
                b[ni][0] = bs[c0 * BSTR + n];
                b[ni][1] = bs[(c0 + 4) * BSTR + n];
            }
            #pragma unroll
            for (int mi = 0; mi < 4; mi++)
                #pragma unroll
                for (int ni = 0; ni < 4; ni++)
                    mma_tf32(d[mi][ni], a[mi], b[ni]);
        }
    }

    #pragma unroll
    for (int mi = 0; mi < 4; mi++) {
        const int r = row0 + wm + mi * 16 + g;
        #pragma unroll
        for (int ni = 0; ni < 4; ni++) {
            const int c = col0 + wn + ni * 8 + 2 * t;
            const float b0 = bias[c], b1 = bias[c + 1];
            float v00 = d[mi][ni][0] + b0, v01 = d[mi][ni][1] + b1;
            float v10 = d[mi][ni][2] + b0, v11 = d[mi][ni][3] + b1;
            if (ROUND) {
                v00 = __uint_as_float(f2tf32(v00));
                v01 = __uint_as_float(f2tf32(v01));
                v10 = __uint_as_float(f2tf32(v10));
                v11 = __uint_as_float(f2tf32(v11));
            }
            *(float2*)&out[(size_t)r * N + c]       = make_float2(v00, v01);
            *(float2*)&out[(size_t)(r + 8) * N + c] = make_float2(v10, v11);
        }
    }
    #undef LOAD_STAGE
}

// ---------------------------------------------------------------------------
// Tensor-core flash attention v2: 256 threads, BQ=128 (8 warps x 16 q-rows),
// cp.async double-buffered KV tiles of 64, Q frags straight from gmem
// (overlapped with first KV load), per-warp causal skip.
// Dynamic smem: K[2][64*KSTR] + V[2][64*VSTR] = 71,680 B.
// ---------------------------------------------------------------------------
#define KSTR 68
#define VSTR 72
#define ATTN_SMEM ((2 * 64 * KSTR + 2 * 64 * VSTR) * 4)

extern __shared__ unsigned attn_smem[];

__global__ __launch_bounds__(256, 2)
void attn_tc2_kernel(const float* __restrict__ qkv, float* __restrict__ out)
{
    unsigned* Kbuf[2];
    unsigned* Vbuf[2];
    Kbuf[0] = attn_smem;
    Kbuf[1] = Kbuf[0] + 64 * KSTR;
    Vbuf[0] = Kbuf[1] + 64 * KSTR;
    Vbuf[1] = Vbuf[0] + 64 * VSTR;

    const int bh  = blockIdx.y;
    const int b   = bh >> 4;
    const int h   = bh & 15;
    const int q0  = (gridDim.x - 1 - blockIdx.x) * 128;   // longest blocks first
    const int tid = threadIdx.x;
    const int lane = tid & 31;
    const int warp = tid >> 5;
    const int g = lane >> 2;
    const int t = lane & 3;

    const size_t rstr = 3 * CC;

    // staging: 8 cp.async (4 K + 4 V) per thread per tile, one commit group
    const int st_row[4] = { (tid + 0) >> 4, (tid + 256) >> 4, (tid + 512) >> 4, (tid + 768) >> 4 };
    const int st_c = (tid & 15) * 4;

    #define STAGE_KV(it, slot) do {                                                        \
        const int kvr = (it) * 64;                                                         \
        _Pragma("unroll")                                                                  \
        for (int i_ = 0; i_ < 4; i_++) {                                                   \
            const int row_ = st_row[i_];                                                   \
            const float* src_ = qkv + (size_t)(b * TT + kvr + row_) * rstr + CC + h * DD + st_c; \
            cp_async16(&Kbuf[slot][row_ * KSTR + st_c], src_);                             \
            cp_async16(&Vbuf[slot][row_ * VSTR + st_c], src_ + CC);                        \
        }                                                                                  \
        asm volatile("cp.async.commit_group;" ::: "memory");                               \
    } while (0)

    // kick off KV tile 0 immediately
    STAGE_KV(0, 0);

    // ---- Q fragments straight from gmem (x 1/8 exact on tf32 values) ----
    const int r_lo = q0 + warp * 16 + g;
    const int r_hi = r_lo + 8;
    unsigned qa[8][4];
    {
        const float* qlo = qkv + (size_t)(b * TT + r_lo) * rstr + h * DD;
        const float* qhi = qlo + 8 * rstr;
        #pragma unroll
        for (int kk = 0; kk < 8; kk++) {
            qa[kk][0] = __float_as_uint(qlo[kk * 8 + t]     * 0.125f);
            qa[kk][1] = __float_as_uint(qhi[kk * 8 + t]     * 0.125f);
            qa[kk][2] = __float_as_uint(qlo[kk * 8 + t + 4] * 0.125f);
            qa[kk][3] = __float_as_uint(qhi[kk * 8 + t + 4] * 0.125f);
        }
    }

    float o[8][4];
    #pragma unroll
    for (int nt = 0; nt < 8; nt++)
        #pragma unroll
        for (int j = 0; j < 4; j++) o[nt][j] = 0.f;
    float m0 = -CUDART_INF_F, m1 = -CUDART_INF_F;
    float l0 = 0.f, l1 = 0.f;

    const int ntiles = q0 / 64 + 2;
    const int kv_end_w = q0 + warp * 16 + 16;   // first kv NOT needed by this warp

    for (int it = 0; it < ntiles; it++) {
        const int kv0 = it * 64;
        asm volatile("cp.async.wait_group 0;" ::: "memory");
        __syncthreads();
        if (it + 1 < ntiles) STAGE_KV(it + 1, (it + 1) & 1);

        if (kv0 < kv_end_w) {
            const unsigned* Kc = Kbuf[it & 1];
            const unsigned* Vc = Vbuf[it & 1];

            // ---- S = Q K^T ----
            float s[8][4];
            #pragma unroll
            for (int nt = 0; nt < 8; nt++) {
                s[nt][0] = 0.f; s[nt][1] = 0.f; s[nt][2] = 0.f; s[nt][3] = 0.f;
                #pragma unroll
                for (int kk = 0; kk < 8; kk++) {
                    unsigned bfr[2];
                    bfr[0] = Kc[(nt * 8 + g) * KSTR + kk * 8 + t];
                    bfr[1] = Kc[(nt * 8 + g) * KSTR + kk * 8 + t + 4];
                    mma_tf32(s[nt], qa[kk], bfr);
                }
            }

            // ---- causal mask (tiles overlapping this warp's rows) ----
            if (kv0 + 64 > r_lo) {
                #pragma unroll
                for (int nt = 0; nt < 8; nt++) {
                    const int c0col = kv0 + nt * 8 + 2 * t;
                    if (c0col     > r_lo) s[nt][0] = -CUDART_INF_F;
                    if (c0col + 1 > r_lo) s[nt][1] = -CUDART_INF_F;
                    if (c0col     > r_hi) s[nt][2] = -CUDART_INF_F;
                    if (c0col + 1 > r_hi) s[nt][3] = -CUDART_INF_F;
                }
            }

            // ---- online softmax ----
            float mx0 = -CUDART_INF_F, mx1 = -CUDART_INF_F;
            #pragma unroll
            for (int nt = 0; nt < 8; nt++) {
                mx0 = fmaxf(mx0, fmaxf(s[nt][0], s[nt][1]));
                mx1 = fmaxf(mx1, fmaxf(s[nt][2], s[nt][3]));
            }
            mx0 = fmaxf(mx0, __shfl_xor_sync(0xffffffffu, mx0, 1));
            mx0 = fmaxf(mx0, __shfl_xor_sync(0xffffffffu, mx0, 2));
            mx1 = fmaxf(mx1, __shfl_xor_sync(0xffffffffu, mx1, 1));
            mx1 = fmaxf(mx1, __shfl_xor_sync(0xffffffffu, mx1, 2));

            const float M0 = fmaxf(m0, mx0), M1 = fmaxf(m1, mx1);
            const float cor0 = __expf(m0 - M0), cor1 = __expf(m1 - M1);
            l0 *= cor0; l1 *= cor1;
            #pragma unroll
            for (int nt = 0; nt < 8; nt++) {
                o[nt][0] *= cor0; o[nt][1] *= cor0;
                o[nt][2] *= cor1; o[nt][3] *= cor1;
            }
            m0 = M0; m1 = M1;

            #pragma unroll
            for (int nt = 0; nt < 8; nt++) {
                s[nt][0] = __expf(s[nt][0] - M0);
                s[nt][1] = __expf(s[nt][1] - M0);
                s[nt][2] = __expf(s[nt][2] - M1);
                s[nt][3] = __expf(s[nt][3] - M1);
                l0 += s[nt][0] + s[nt][1];
                l1 += s[nt][2] + s[nt][3];
            }

            // ---- O += P V : C-frag -> A-frag via quad shfl, then MMA ----
            const int srcA = (lane & 28) | (t >> 1);
            const int srcB = srcA + 2;
            const bool hi = (t & 1);
            #pragma unroll
            for (int kk = 0; kk < 8; kk++) {
                const float x0 = __shfl_sync(0xffffffffu, s[kk][0], srcA);
                const float x1 = __shfl_sync(0xffffffffu, s[kk][1], srcA);
                const float x2 = __shfl_sync(0xffffffffu, s[kk][2], srcA);
                const float x3 = __shfl_sync(0xffffffffu, s[kk][3], srcA);
                const float y0 = __shfl_sync(0xffffffffu, s[kk][0], srcB);
                const float y1 = __shfl_sync(0xffffffffu, s[kk][1], srcB);
                const float y2 = __shfl_sync(0xffffffffu, s[kk][2], srcB);
                const float y3 = __shfl_sync(0xffffffffu, s[kk][3], srcB);
                unsigned pa[4];
                pa[0] = f2tf32(hi ? x1 : x0);
                pa[1] = f2tf32(hi ? x3 : x2);
                pa[2] = f2tf32(hi ? y1 : y0);
                pa[3] = f2tf32(hi ? y3 : y2);
                #pragma unroll
                for (int nt2 = 0; nt2 < 8; nt2++) {
                    unsigned bfr[2];
                    bfr[0] = Vc[(kk * 8 + t) * VSTR + nt2 * 8 + g];
                    bfr[1] = Vc[(kk * 8 + t + 4) * VSTR + nt2 * 8 + g];
                    mma_tf32(o[nt2], pa, bfr);
                }
            }
        }
        __syncthreads();   // all reads of this slot done before it is re-staged
    }
    #undef STAGE_KV

    // ---- finalize: reduce l across quad, normalize, store tf32-rounded ----
    l0 += __shfl_xor_sync(0xffffffffu, l0, 1);
    l0 += __shfl_xor_sync(0xffffffffu, l0, 2);
    l1 += __shfl_xor_sync(0xffffffffu, l1, 1);
    l1 += __shfl_xor_sync(0xffffffffu, l1, 2);
    const float inv0 = 1.f / l0, inv1 = 1.f / l1;

    float* op_lo = out + ((size_t)(b * TT + r_lo)) * CC + h * DD;
    float* op_hi = out + ((size_t)(b * TT + r_hi)) * CC + h * DD;
    #pragma unroll
    for (int nt2 = 0; nt2 < 8; nt2++) {
        const int c = nt2 * 8 + 2 * t;
        float2 vlo = make_float2(__uint_as_float(f2tf32(o[nt2][0] * inv0)),
                                 __uint_as_float(f2tf32(o[nt2][1] * inv0)));
        float2 vhi = make_float2(__uint_as_float(f2tf32(o[nt2][2] * inv1)),
                                 __uint_as_float(f2tf32(o[nt2][3] * inv1)));
        *(float2*)&op_lo[c] = vlo;
        *(float2*)&op_hi[c] = vhi;
    }
}

// ---------------------------------------------------------------------------
// Launch
// ---------------------------------------------------------------------------
extern "C" void kernel_launch(void* const* d_in, const int* in_sizes, int n_in,
                              void* d_out, int out_size)
{
    const float* hidden = (const float*)d_in[0];   // [B,T,C]
    const float* qkv_w  = (const float*)d_in[1];   // [C, 3C]
    const float* qkv_b  = (const float*)d_in[2];   // [3C]
    const float* o_w    = (const float*)d_in[3];   // [C, C]
    const float* o_b    = (const float*)d_in[4];   // [C]
    float* out = (float*)d_out;                    // [B,T,C]

    float *qkv, *attn, *x, *w1, *w2;
    cudaGetSymbolAddress((void**)&qkv,  g_qkv);
    cudaGetSymbolAddress((void**)&attn, g_attn);
    cudaGetSymbolAddress((void**)&x,    g_x);
    cudaGetSymbolAddress((void**)&w1,   g_w1);
    cudaGetSymbolAddress((void**)&w2,   g_w2);

    // 0) pre-convert operands to tf32
    {
        int n4;
        n4 = BTOT * CC / 4;
        cvt_tf32_kernel<<<(n4 + 255) / 256, 256>>>((const float4*)hidden, (float4*)x, n4);
        n4 = CC * 3 * CC / 4;
        cvt_tf32_kernel<<<(n4 + 255) / 256, 256>>>((const float4*)qkv_w, (float4*)w1, n4);
        n4 = CC * CC / 4;
        cvt_tf32_kernel<<<(n4 + 255) / 256, 256>>>((const float4*)o_w, (float4*)w2, n4);
    }
    // 1) QKV projection (output tf32-rounded for the attention kernel)
    {
        dim3 grid(3 * CC / 128, BTOT / 128);
        gemm_tf32_pipe<true><<<grid, 256>>>(x, w1, qkv_b, qkv, BTOT, 3 * CC, CC);
    }
    // 2) Causal multi-head attention (tensor cores, cp.async pipelined)
    {
        cudaFuncSetAttribute(attn_tc2_kernel,
                             cudaFuncAttributeMaxDynamicSharedMemorySize, ATTN_SMEM);
        dim3 grid(TT / 128, BB * HH);
        attn_tc2_kernel<<<grid, 256, ATTN_SMEM>>>(qkv, attn);
    }
    // 3) Output projection (full fp32 output)
    {
        dim3 grid(CC / 128, BTOT / 128);
        gemm_tf32_pipe<false><<<grid, 256>>>(attn, w2, o_b, out, BTOT, CC, CC);
    }
}